// round 6
// baseline (speedup 1.0000x reference)
#include <cuda_runtime.h>
#include <cuda_fp16.h>
#include <cstdint>

// ---------------------------------------------------------------------------
// RN discriminator (sm_100-target-safe mma.sync HMMA path):
//   x (B=64,64pos,26ch) -> u = x@W1_top+b1, v = x@W1_bot   (64,64,256)
//   pair GEMM: per (b, i-pair): A=relu(u_j+v_i) fp16 [128x256],
//     D = A @ (W2_hi + W2_lo)  (fp32 acc; W2 split kills systematic fp16 err),
//     epilogue relu(D+b2) column-summed -> d_part
//   512 threads / 16 warps per CTA (warp tile 64x32) for tensor-pipe latency
//   hiding; acc 64 regs/thread so the whole CTA fits the 64K regfile.
// ---------------------------------------------------------------------------

#define NB   64
#define NPOS 64
#define NC2  26
#define GH   256

__device__ float d_x[NB * NPOS * NC2];
__device__ float d_u[NB * NPOS * GH];
__device__ float d_v[NB * NPOS * GH];
__device__ float d_part[NB * NPOS * GH];
__device__ float d_pool[NB * 4 * GH];
// W2^T fp16 hi/lo: [kt(4)] { hi: n(256) x 128B swz | lo: same } = 64KB per kt
__device__ unsigned char d_w2t[4 * 65536];

// ---------------- PTX helpers ----------------------------------------------
__device__ __forceinline__ uint32_t cvta_smem(const void* p) {
    uint32_t a;
    asm("{ .reg .u64 t; cvta.to.shared.u64 t, %1; cvt.u32.u64 %0, t; }"
        : "=r"(a) : "l"(p));
    return a;
}
__device__ __forceinline__ void cpasync16(uint32_t dst, const void* src) {
    asm volatile("cp.async.cg.shared.global [%0], [%1], 16;"
                 :: "r"(dst), "l"(src) : "memory");
}
__device__ __forceinline__ void ldsm4(uint32_t* r, uint32_t addr) {
    asm volatile("ldmatrix.sync.aligned.m8n8.x4.shared.b16 {%0,%1,%2,%3}, [%4];"
                 : "=r"(r[0]), "=r"(r[1]), "=r"(r[2]), "=r"(r[3]) : "r"(addr));
}
__device__ __forceinline__ void mma16816(float* c, const uint32_t* a,
                                         const uint32_t* b) {
    asm volatile(
        "mma.sync.aligned.m16n8k16.row.col.f32.f16.f16.f32 "
        "{%0,%1,%2,%3}, {%4,%5,%6,%7}, {%8,%9}, {%0,%1,%2,%3};"
        : "+f"(c[0]), "+f"(c[1]), "+f"(c[2]), "+f"(c[3])
        : "r"(a[0]), "r"(a[1]), "r"(a[2]), "r"(a[3]), "r"(b[0]), "r"(b[1]));
}

// ---------------- Kernel A: conv 8x8 stride 8 + relu + coords ---------------
__global__ __launch_bounds__(256)
void conv_kernel(const float* __restrict__ img,
                 const float* __restrict__ w,
                 const float* __restrict__ bias) {
    __shared__ float s_img[3 * 64 * 64];
    const int b   = blockIdx.x;
    const int tid = threadIdx.x;

    const float* gsrc = img + b * (3 * 64 * 64);
    #pragma unroll
    for (int it = 0; it < 48; ++it)
        s_img[it * 256 + tid] = gsrc[it * 256 + tid];
    __syncthreads();

    const int pos = tid & 63;
    const int r   = pos >> 3;
    const int cc  = pos & 7;
    const int o0  = tid >> 6;

    for (int oo = 0; oo < 6; ++oo) {
        const int o = o0 + oo * 4;
        float acc = bias[o];
        for (int c = 0; c < 3; ++c) {
            #pragma unroll
            for (int ky = 0; ky < 8; ++ky) {
                #pragma unroll
                for (int kx = 0; kx < 8; ++kx) {
                    acc += s_img[(c * 64 + r * 8 + ky) * 64 + cc * 8 + kx]
                         * __ldg(&w[((o * 3 + c) * 8 + ky) * 8 + kx]);
                }
            }
        }
        d_x[(b * NPOS + pos) * NC2 + o] = fmaxf(acc, 0.0f);
    }
    if (tid < 64) {
        const int p = tid;
        d_x[(b * NPOS + p) * NC2 + 24] = -1.0f + (2.0f / 7.0f) * (float)(p & 7);
        d_x[(b * NPOS + p) * NC2 + 25] = -1.0f + (2.0f / 7.0f) * (float)(p >> 3);
    }
}

// ---------------- Kernel B: u/v projections ---------------------------------
__global__ __launch_bounds__(256)
void uv_kernel(const float* __restrict__ g_w1,
               const float* __restrict__ g_b1) {
    const int bj  = blockIdx.x;
    const int tid = threadIdx.x;

    __shared__ float xr[NC2];
    if (tid < NC2) xr[tid] = d_x[bj * NC2 + tid];
    __syncthreads();

    float au = g_b1[tid];
    float av = 0.0f;
    #pragma unroll
    for (int k = 0; k < NC2; ++k) {
        const float xv = xr[k];
        au += xv * g_w1[k * GH + tid];
        av += xv * g_w1[(NC2 + k) * GH + tid];
    }
    d_u[bj * GH + tid] = au;
    d_v[bj * GH + tid] = av;
}

// ---------------- Kernel B2: W2^T fp16 hi/lo, pre-swizzled ------------------
__global__ __launch_bounds__(256)
void w2_prep(const float* __restrict__ w2) {
    const int n = blockIdx.x;          // output channel (B row, n-major)
    const int k = threadIdx.x;         // K index
    const float val = w2[k * GH + n];
    const __half hi = __float2half_rn(val);
    const __half lo = __float2half_rn(val - __half2float(hi));
    const int kt = k >> 6;
    const int c  = (k >> 3) & 7;       // 16B chunk within 64-K block
    const int e  = k & 7;
    const uint32_t off = (uint32_t)(n * 128 + ((c ^ (n & 7)) << 4) + e * 2);
    *(__half*)(d_w2t + kt * 65536 + off)         = hi;
    *(__half*)(d_w2t + kt * 65536 + 32768 + off) = lo;
}

// ---------------- Kernel C: mma.sync pair GEMM (W2 hi/lo) -------------------
// dynamic smem: A fp16 [128][256] swizzled      = 65536
//               B ring: 2 stages x {hi|lo} 64KB = 131072
//               red [2][256] f32                = 2048
#define SOFF_B    65536
#define SOFF_RED  196608
#define SMEM_PAIR 198656

extern __shared__ unsigned char smp[];

__global__ __launch_bounds__(512, 1)
void pair_mma(const float* __restrict__ b2) {
    const int tid  = threadIdx.x;
    const int wid  = tid >> 5;
    const int lane = tid & 31;
    const int i0   = blockIdx.x * 2;
    const int b    = blockIdx.y;
    const uint32_t sbase = cvta_smem(smp);

    // warp grid 2(M) x 8(N); warp tile 64 x 32
    const int warp_m = wid >> 3;
    const int warp_n = wid & 7;
    const int laneA_row  = warp_m * 64 + (lane & 7) + ((lane >> 3) & 1) * 8;
    const int laneA_cofs = lane >> 4;
    const int laneB_row  = warp_n * 32 + (lane & 7) + ((lane >> 4) << 3);
    const int laneB_cofs = (lane >> 3) & 1;

    // stage loader: 64KB (hi|lo of one kt) via 8 cp.async per thread
    auto issue_stage = [&](int kt, int slot) {
        const unsigned char* gsrc = d_w2t + kt * 65536;
        const uint32_t dst = sbase + SOFF_B + slot * 65536;
        #pragma unroll
        for (int it = 0; it < 8; ++it) {
            const int off = (it * 512 + tid) * 16;
            cpasync16(dst + off, gsrc + off);
        }
        asm volatile("cp.async.commit_group;" ::: "memory");
    };

    issue_stage(0, 0);
    issue_stage(1, 1);

    // ---- build A = relu(u_j + v_i) fp16, swizzled 16B chunks ----
    {
        const int r = tid >> 2;                 // 0..127
        const int q = tid & 3;                  // K quarter (64 cols)
        const int j = r & 63;
        const int isel = i0 + (r >> 6);
        const float4* u4 = (const float4*)(d_u + (size_t)(b * NPOS + j) * GH + q * 64);
        const float4* v4 = (const float4*)(d_v + (size_t)(b * NPOS + isel) * GH + q * 64);
        #pragma unroll
        for (int cc = 0; cc < 8; ++cc) {
            const float4 ua = u4[cc * 2],     va = v4[cc * 2];
            const float4 ub = u4[cc * 2 + 1], vb = v4[cc * 2 + 1];
            __half2 h0 = __floats2half2_rn(fmaxf(ua.x + va.x, 0.f), fmaxf(ua.y + va.y, 0.f));
            __half2 h1 = __floats2half2_rn(fmaxf(ua.z + va.z, 0.f), fmaxf(ua.w + va.w, 0.f));
            __half2 h2 = __floats2half2_rn(fmaxf(ub.x + vb.x, 0.f), fmaxf(ub.y + vb.y, 0.f));
            __half2 h3 = __floats2half2_rn(fmaxf(ub.z + vb.z, 0.f), fmaxf(ub.w + vb.w, 0.f));
            const int c = q * 8 + cc;           // 16B chunk index 0..31
            uint4 val;
            val.x = *reinterpret_cast<uint32_t*>(&h0);
            val.y = *reinterpret_cast<uint32_t*>(&h1);
            val.z = *reinterpret_cast<uint32_t*>(&h2);
            val.w = *reinterpret_cast<uint32_t*>(&h3);
            *(uint4*)(smp + r * 512 + ((c ^ (r & 7)) << 4)) = val;
        }
    }

    float acc[4][4][4];
    #pragma unroll
    for (int mt = 0; mt < 4; ++mt)
        #pragma unroll
        for (int nt = 0; nt < 4; ++nt)
            #pragma unroll
            for (int q = 0; q < 4; ++q) acc[mt][nt][q] = 0.0f;

    // compute one kt stage (hi + lo products into same acc)
    auto compute_stage = [&](int kt, int slot) {
        const uint32_t bb = sbase + SOFF_B + slot * 65536;
        #pragma unroll
        for (int ks = 0; ks < 4; ++ks) {
            uint32_t aF[4][4], bF[2][4];
            const int cA = kt * 8 + ks * 2 + laneA_cofs;
            #pragma unroll
            for (int mt = 0; mt < 4; ++mt) {
                const int row = laneA_row + mt * 16;
                ldsm4(aF[mt], sbase + row * 512 + ((cA ^ (row & 7)) << 4));
            }
            const int cB = ks * 2 + laneB_cofs;
            #pragma unroll
            for (int ng = 0; ng < 2; ++ng) {
                const int row = laneB_row + ng * 16;
                ldsm4(bF[ng], bb + row * 128 + ((cB ^ (row & 7)) << 4));
            }
            #pragma unroll
            for (int mt = 0; mt < 4; ++mt)
                #pragma unroll
                for (int nt = 0; nt < 4; ++nt)
                    mma16816(acc[mt][nt], aF[mt], &bF[nt >> 1][(nt & 1) * 2]);
            // lo part
            #pragma unroll
            for (int ng = 0; ng < 2; ++ng) {
                const int row = laneB_row + ng * 16;
                ldsm4(bF[ng], bb + 32768 + row * 128 + ((cB ^ (row & 7)) << 4));
            }
            #pragma unroll
            for (int mt = 0; mt < 4; ++mt)
                #pragma unroll
                for (int nt = 0; nt < 4; ++nt)
                    mma16816(acc[mt][nt], aF[mt], &bF[nt >> 1][(nt & 1) * 2]);
        }
    };

    asm volatile("cp.async.wait_group 1;" ::: "memory");   // g0 done
    __syncthreads();                                       // A + stage0 visible
    compute_stage(0, 0);
    __syncthreads();                                       // stage0 consumed
    issue_stage(2, 0);
    asm volatile("cp.async.wait_group 1;" ::: "memory");   // g1 done
    __syncthreads();
    compute_stage(1, 1);
    __syncthreads();                                       // stage1 consumed
    issue_stage(3, 1);
    asm volatile("cp.async.wait_group 1;" ::: "memory");   // g2 done
    __syncthreads();
    compute_stage(2, 0);
    asm volatile("cp.async.wait_group 0;" ::: "memory");   // g3 done
    __syncthreads();
    compute_stage(3, 1);

    // ---- epilogue: relu(acc + b2), column sums over 64 j-rows ----
    float* red = (float*)(smp + SOFF_RED);
    #pragma unroll
    for (int nt = 0; nt < 4; ++nt) {
        const int colg = warp_n * 32 + nt * 8 + (lane & 3) * 2;
        const float b0v = __ldg(&b2[colg]);
        const float b1v = __ldg(&b2[colg + 1]);
        float p0 = 0.0f, p1 = 0.0f;
        #pragma unroll
        for (int mt = 0; mt < 4; ++mt) {
            p0 += fmaxf(acc[mt][nt][0] + b0v, 0.f) + fmaxf(acc[mt][nt][2] + b0v, 0.f);
            p1 += fmaxf(acc[mt][nt][1] + b1v, 0.f) + fmaxf(acc[mt][nt][3] + b1v, 0.f);
        }
        #pragma unroll
        for (int m = 4; m < 32; m <<= 1) {
            p0 += __shfl_xor_sync(0xffffffffu, p0, m);
            p1 += __shfl_xor_sync(0xffffffffu, p1, m);
        }
        if (lane < 4) {
            red[warp_m * 256 + colg]     = p0;
            red[warp_m * 256 + colg + 1] = p1;
        }
    }
    __syncthreads();
    if (tid < 256) {
        d_part[(size_t)(b * NPOS + i0) * GH + tid]     = red[tid];
        d_part[(size_t)(b * NPOS + i0 + 1) * GH + tid] = red[256 + tid];
    }
}

// ---------------- Kernel D1: partial pooling --------------------------------
__global__ __launch_bounds__(256)
void pool_kernel() {
    const int b = blockIdx.x, q = blockIdx.y;
    const int tid = threadIdx.x;
    float s = 0.0f;
    #pragma unroll
    for (int i = 0; i < 16; ++i)
        s += d_part[(size_t)(b * NPOS + q * 16 + i) * GH + tid];
    d_pool[(size_t)(b * 4 + q) * GH + tid] = s;
}

// ---------------- Kernel D2: f head -----------------------------------------
__global__ __launch_bounds__(256)
void head_kernel(const float* __restrict__ f_w1,
                 const float* __restrict__ f_b1,
                 const float* __restrict__ f_w2,
                 const float* __restrict__ f_b2,
                 float* __restrict__ out) {
    const int b   = blockIdx.x;
    const int tid = threadIdx.x;

    __shared__ float pooled[GH];
    __shared__ float red[256];

    pooled[tid] = d_pool[(size_t)(b * 4 + 0) * GH + tid]
                + d_pool[(size_t)(b * 4 + 1) * GH + tid]
                + d_pool[(size_t)(b * 4 + 2) * GH + tid]
                + d_pool[(size_t)(b * 4 + 3) * GH + tid];
    __syncthreads();

    float a0 = 0.f, a1 = 0.f, a2 = 0.f, a3 = 0.f;
    #pragma unroll 4
    for (int kk = 0; kk < 64; ++kk) {
        const int k = kk * 4;
        a0 += pooled[k]     * f_w1[(k)     * GH + tid];
        a1 += pooled[k + 1] * f_w1[(k + 1) * GH + tid];
        a2 += pooled[k + 2] * f_w1[(k + 2) * GH + tid];
        a3 += pooled[k + 3] * f_w1[(k + 3) * GH + tid];
    }
    const float h = fmaxf((a0 + a1) + (a2 + a3) + f_b1[tid], 0.0f) * f_w2[tid];

    red[tid] = h;
    __syncthreads();
    #pragma unroll
    for (int s = 128; s > 0; s >>= 1) {
        if (tid < s) red[tid] += red[tid + s];
        __syncthreads();
    }
    if (tid == 0) out[b] = red[0] + f_b2[0];
}

// ---------------------------------------------------------------------------
extern "C" void kernel_launch(void* const* d_in, const int* in_sizes, int n_in,
                              void* d_out, int out_size) {
    const float* image  = (const float*)d_in[0];
    const float* conv_w = (const float*)d_in[1];
    const float* conv_b = (const float*)d_in[2];
    const float* g_w1   = (const float*)d_in[3];
    const float* g_b1   = (const float*)d_in[4];
    const float* g_w2   = (const float*)d_in[5];
    const float* g_b2   = (const float*)d_in[6];
    const float* f_w1   = (const float*)d_in[7];
    const float* f_b1   = (const float*)d_in[8];
    const float* f_w2   = (const float*)d_in[9];
    const float* f_b2   = (const float*)d_in[10];
    float* out = (float*)d_out;

    static bool attr_done = false;
    if (!attr_done) {
        cudaFuncSetAttribute(pair_mma,
                             cudaFuncAttributeMaxDynamicSharedMemorySize, SMEM_PAIR);
        attr_done = true;
    }

    conv_kernel<<<NB, 256>>>(image, conv_w, conv_b);
    w2_prep<<<GH, GH>>>(g_w2);
    uv_kernel<<<NB * NPOS, 256>>>(g_w1, g_b1);
    pair_mma<<<dim3(NPOS / 2, NB), 512, SMEM_PAIR>>>(g_b2);
    pool_kernel<<<dim3(NB, 4), 256>>>();
    head_kernel<<<NB, 256>>>(f_w1, f_b1, f_w2, f_b2, out);
}

// round 7
// speedup vs baseline: 1.3617x; 1.3617x over previous
#include <cuda_runtime.h>
#include <cuda_fp16.h>
#include <cstdint>

// ---------------------------------------------------------------------------
// RN discriminator (sm_100-target-safe mma.sync HMMA path):
//   x (B=64,64pos,26ch) -> u16 = fp16(x@W1_top+b1), v16 = fp16(x@W1_bot)
//   pair GEMM: CTA = one (b,i): A=relu(u_j+v_i) fp16 [64x256],
//     D = A @ (W2_hi + W2_lo) (fp32 acc), epilogue relu(D+b2) col-sum -> d_part
//   96KB smem/CTA -> 2 CTAs/SM: phases of one CTA overlap MMAs of the other.
// ---------------------------------------------------------------------------

#define NB   64
#define NPOS 64
#define NC2  26
#define GH   256

__device__ float  d_x[NB * NPOS * NC2];
__device__ __half d_u16[NB * NPOS * GH];
__device__ __half d_v16[NB * NPOS * GH];
__device__ float  d_part[NB * NPOS * GH];
__device__ float  d_pool[NB * 4 * GH];
// W2^T fp16 hi/lo: [kt(4)] { hi: n(256) x 128B swz | lo: same } = 64KB per kt
__device__ unsigned char d_w2t[4 * 65536];

// ---------------- PTX helpers ----------------------------------------------
__device__ __forceinline__ uint32_t cvta_smem(const void* p) {
    uint32_t a;
    asm("{ .reg .u64 t; cvta.to.shared.u64 t, %1; cvt.u32.u64 %0, t; }"
        : "=r"(a) : "l"(p));
    return a;
}
__device__ __forceinline__ void cpasync16(uint32_t dst, const void* src) {
    asm volatile("cp.async.cg.shared.global [%0], [%1], 16;"
                 :: "r"(dst), "l"(src) : "memory");
}
__device__ __forceinline__ void ldsm4(uint32_t* r, uint32_t addr) {
    asm volatile("ldmatrix.sync.aligned.m8n8.x4.shared.b16 {%0,%1,%2,%3}, [%4];"
                 : "=r"(r[0]), "=r"(r[1]), "=r"(r[2]), "=r"(r[3]) : "r"(addr));
}
__device__ __forceinline__ void mma16816(float* c, const uint32_t* a,
                                         const uint32_t* b) {
    asm volatile(
        "mma.sync.aligned.m16n8k16.row.col.f32.f16.f16.f32 "
        "{%0,%1,%2,%3}, {%4,%5,%6,%7}, {%8,%9}, {%0,%1,%2,%3};"
        : "+f"(c[0]), "+f"(c[1]), "+f"(c[2]), "+f"(c[3])
        : "r"(a[0]), "r"(a[1]), "r"(a[2]), "r"(a[3]), "r"(b[0]), "r"(b[1]));
}

// ---------------- Kernel A: conv 8x8 stride 8 + relu + coords ---------------
__global__ __launch_bounds__(256)
void conv_kernel(const float* __restrict__ img,
                 const float* __restrict__ w,
                 const float* __restrict__ bias) {
    __shared__ float s_img[3 * 64 * 64];
    const int b   = blockIdx.x;
    const int tid = threadIdx.x;

    const float* gsrc = img + b * (3 * 64 * 64);
    #pragma unroll
    for (int it = 0; it < 48; ++it)
        s_img[it * 256 + tid] = gsrc[it * 256 + tid];
    __syncthreads();

    const int pos = tid & 63;
    const int r   = pos >> 3;
    const int cc  = pos & 7;
    const int o0  = tid >> 6;

    for (int oo = 0; oo < 6; ++oo) {
        const int o = o0 + oo * 4;
        float acc = bias[o];
        for (int c = 0; c < 3; ++c) {
            #pragma unroll
            for (int ky = 0; ky < 8; ++ky) {
                #pragma unroll
                for (int kx = 0; kx < 8; ++kx) {
                    acc += s_img[(c * 64 + r * 8 + ky) * 64 + cc * 8 + kx]
                         * __ldg(&w[((o * 3 + c) * 8 + ky) * 8 + kx]);
                }
            }
        }
        d_x[(b * NPOS + pos) * NC2 + o] = fmaxf(acc, 0.0f);
    }
    if (tid < 64) {
        const int p = tid;
        d_x[(b * NPOS + p) * NC2 + 24] = -1.0f + (2.0f / 7.0f) * (float)(p & 7);
        d_x[(b * NPOS + p) * NC2 + 25] = -1.0f + (2.0f / 7.0f) * (float)(p >> 3);
    }
}

// ---------------- Kernel B: u/v projections (fp16 out) ----------------------
__global__ __launch_bounds__(256)
void uv_kernel(const float* __restrict__ g_w1,
               const float* __restrict__ g_b1) {
    const int bj  = blockIdx.x;
    const int tid = threadIdx.x;

    __shared__ float xr[NC2];
    if (tid < NC2) xr[tid] = d_x[bj * NC2 + tid];
    __syncthreads();

    float au = g_b1[tid];
    float av = 0.0f;
    #pragma unroll
    for (int k = 0; k < NC2; ++k) {
        const float xv = xr[k];
        au += xv * g_w1[k * GH + tid];
        av += xv * g_w1[(NC2 + k) * GH + tid];
    }
    d_u16[bj * GH + tid] = __float2half_rn(au);
    d_v16[bj * GH + tid] = __float2half_rn(av);
}

// ---------------- Kernel B2: W2^T fp16 hi/lo, pre-swizzled ------------------
__global__ __launch_bounds__(256)
void w2_prep(const float* __restrict__ w2) {
    const int n = blockIdx.x;          // output channel (B row, n-major)
    const int k = threadIdx.x;         // K index
    const float val = w2[k * GH + n];
    const __half hi = __float2half_rn(val);
    const __half lo = __float2half_rn(val - __half2float(hi));
    const int kt = k >> 6;
    const int c  = (k >> 3) & 7;       // 16B chunk within 64-K block
    const int e  = k & 7;
    const uint32_t off = (uint32_t)(n * 128 + ((c ^ (n & 7)) << 4) + e * 2);
    *(__half*)(d_w2t + kt * 65536 + off)         = hi;
    *(__half*)(d_w2t + kt * 65536 + 32768 + off) = lo;
}

// ---------------- Kernel C: mma.sync pair GEMM ------------------------------
// dynamic smem: A fp16 [64][256] swizzled = 32768
//               B ring: 2 x 32KB stages   = 65536   -> 96KB, 2 CTAs/SM
#define SOFF_B    32768
#define SMEM_PAIR (32768 + 65536)

extern __shared__ unsigned char smp[];

__global__ __launch_bounds__(128, 2)
void pair_mma(const float* __restrict__ b2) {
    const int tid  = threadIdx.x;
    const int wid  = tid >> 5;          // warp 0..3 = n-slice
    const int lane = tid & 31;
    const int i    = blockIdx.x;
    const int b    = blockIdx.y;
    const uint32_t sbase = cvta_smem(smp);

    const int laneA_row  = (lane & 7) + ((lane >> 3) & 1) * 8;
    const int laneA_cofs = lane >> 4;
    const int laneB_row  = wid * 64 + (lane & 7) + ((lane >> 4) << 3);
    const int laneB_cofs = (lane >> 3) & 1;

    // stage s (0..7): kt = s>>1, part = s&1 (hi/lo); 32KB contiguous in d_w2t
    auto issue_stage = [&](int s) {
        const unsigned char* gsrc = d_w2t + (s >> 1) * 65536 + (s & 1) * 32768;
        const uint32_t dst = sbase + SOFF_B + (s & 1) * 32768;
        #pragma unroll
        for (int it = 0; it < 16; ++it) {
            const int off = (it * 128 + tid) * 16;
            cpasync16(dst + off, gsrc + off);
        }
        asm volatile("cp.async.commit_group;" ::: "memory");
    };

    issue_stage(0);
    issue_stage(1);

    // ---- build A = relu(u16_j + v16_i), swizzled 16B chunks ----
    {
        const int r  = tid >> 1;                 // j row 0..63
        const int hf = tid & 1;                  // K half
        const uint4* u4 = (const uint4*)(d_u16 + (size_t)(b * NPOS + r) * GH + hf * 128);
        const uint4* v4 = (const uint4*)(d_v16 + (size_t)(b * NPOS + i) * GH + hf * 128);
        const __half2 zero2 = __floats2half2_rn(0.f, 0.f);
        #pragma unroll
        for (int cc = 0; cc < 16; ++cc) {
            const uint4 uu = u4[cc];
            const uint4 vv = v4[cc];
            uint4 res;
            __half2 t;
            t = __hmax2(__hadd2(*(const __half2*)&uu.x, *(const __half2*)&vv.x), zero2);
            res.x = *(uint32_t*)&t;
            t = __hmax2(__hadd2(*(const __half2*)&uu.y, *(const __half2*)&vv.y), zero2);
            res.y = *(uint32_t*)&t;
            t = __hmax2(__hadd2(*(const __half2*)&uu.z, *(const __half2*)&vv.z), zero2);
            res.z = *(uint32_t*)&t;
            t = __hmax2(__hadd2(*(const __half2*)&uu.w, *(const __half2*)&vv.w), zero2);
            res.w = *(uint32_t*)&t;
            const int c = hf * 16 + cc;          // chunk 0..31
            *(uint4*)(smp + r * 512 + ((c ^ (r & 7)) << 4)) = res;
        }
    }

    float acc[4][8][4];
    #pragma unroll
    for (int mt = 0; mt < 4; ++mt)
        #pragma unroll
        for (int nt = 0; nt < 8; ++nt)
            #pragma unroll
            for (int q = 0; q < 4; ++q) acc[mt][nt][q] = 0.0f;

    auto compute_stage = [&](int s) {
        const int kt = s >> 1;
        const uint32_t bb = sbase + SOFF_B + (s & 1) * 32768;
        #pragma unroll
        for (int ks = 0; ks < 4; ++ks) {
            uint32_t aF[4][4], bF[4][4];
            const int cA = kt * 8 + ks * 2 + laneA_cofs;
            #pragma unroll
            for (int mt = 0; mt < 4; ++mt) {
                const int row = laneA_row + mt * 16;
                ldsm4(aF[mt], sbase + row * 512 + ((cA ^ (row & 7)) << 4));
            }
            const int cB = ks * 2 + laneB_cofs;
            #pragma unroll
            for (int ng = 0; ng < 4; ++ng) {
                const int row = laneB_row + ng * 16;
                ldsm4(bF[ng], bb + row * 128 + ((cB ^ (row & 7)) << 4));
            }
            #pragma unroll
            for (int mt = 0; mt < 4; ++mt)
                #pragma unroll
                for (int nt = 0; nt < 8; ++nt)
                    mma16816(acc[mt][nt], aF[mt], &bF[nt >> 1][(nt & 1) * 2]);
        }
    };

    asm volatile("cp.async.wait_group 1;" ::: "memory");   // stage 0 arrived
    __syncthreads();                                       // A + stage0 visible
    #pragma unroll
    for (int s = 0; s < 8; ++s) {
        compute_stage(s);
        if (s < 6) {
            __syncthreads();                               // slot (s&1) consumed
            issue_stage(s + 2);
            asm volatile("cp.async.wait_group 1;" ::: "memory");
            __syncthreads();
        } else if (s == 6) {
            asm volatile("cp.async.wait_group 0;" ::: "memory");
            __syncthreads();
        }
    }

    // ---- epilogue: relu(acc + b2), column sums over 64 j-rows ----
    float* dst = d_part + (size_t)(b * NPOS + i) * GH;
    #pragma unroll
    for (int nt = 0; nt < 8; ++nt) {
        const int colg = wid * 64 + nt * 8 + (lane & 3) * 2;
        const float b0v = __ldg(&b2[colg]);
        const float b1v = __ldg(&b2[colg + 1]);
        float p0 = 0.0f, p1 = 0.0f;
        #pragma unroll
        for (int mt = 0; mt < 4; ++mt) {
            p0 += fmaxf(acc[mt][nt][0] + b0v, 0.f) + fmaxf(acc[mt][nt][2] + b0v, 0.f);
            p1 += fmaxf(acc[mt][nt][1] + b1v, 0.f) + fmaxf(acc[mt][nt][3] + b1v, 0.f);
        }
        #pragma unroll
        for (int m = 4; m < 32; m <<= 1) {
            p0 += __shfl_xor_sync(0xffffffffu, p0, m);
            p1 += __shfl_xor_sync(0xffffffffu, p1, m);
        }
        if (lane < 4) {
            dst[colg]     = p0;
            dst[colg + 1] = p1;
        }
    }
}

// ---------------- Kernel D1: partial pooling --------------------------------
__global__ __launch_bounds__(256)
void pool_kernel() {
    const int b = blockIdx.x, q = blockIdx.y;
    const int tid = threadIdx.x;
    float s = 0.0f;
    #pragma unroll
    for (int i = 0; i < 16; ++i)
        s += d_part[(size_t)(b * NPOS + q * 16 + i) * GH + tid];
    d_pool[(size_t)(b * 4 + q) * GH + tid] = s;
}

// ---------------- Kernel D2: f head -----------------------------------------
__global__ __launch_bounds__(256)
void head_kernel(const float* __restrict__ f_w1,
                 const float* __restrict__ f_b1,
                 const float* __restrict__ f_w2,
                 const float* __restrict__ f_b2,
                 float* __restrict__ out) {
    const int b   = blockIdx.x;
    const int tid = threadIdx.x;

    __shared__ float pooled[GH];
    __shared__ float red[256];

    pooled[tid] = d_pool[(size_t)(b * 4 + 0) * GH + tid]
                + d_pool[(size_t)(b * 4 + 1) * GH + tid]
                + d_pool[(size_t)(b * 4 + 2) * GH + tid]
                + d_pool[(size_t)(b * 4 + 3) * GH + tid];
    __syncthreads();

    float a0 = 0.f, a1 = 0.f, a2 = 0.f, a3 = 0.f;
    #pragma unroll 4
    for (int kk = 0; kk < 64; ++kk) {
        const int k = kk * 4;
        a0 += pooled[k]     * f_w1[(k)     * GH + tid];
        a1 += pooled[k + 1] * f_w1[(k + 1) * GH + tid];
        a2 += pooled[k + 2] * f_w1[(k + 2) * GH + tid];
        a3 += pooled[k + 3] * f_w1[(k + 3) * GH + tid];
    }
    const float h = fmaxf((a0 + a1) + (a2 + a3) + f_b1[tid], 0.0f) * f_w2[tid];

    red[tid] = h;
    __syncthreads();
    #pragma unroll
    for (int s = 128; s > 0; s >>= 1) {
        if (tid < s) red[tid] += red[tid + s];
        __syncthreads();
    }
    if (tid == 0) out[b] = red[0] + f_b2[0];
}

// ---------------------------------------------------------------------------
extern "C" void kernel_launch(void* const* d_in, const int* in_sizes, int n_in,
                              void* d_out, int out_size) {
    const float* image  = (const float*)d_in[0];
    const float* conv_w = (const float*)d_in[1];
    const float* conv_b = (const float*)d_in[2];
    const float* g_w1   = (const float*)d_in[3];
    const float* g_b1   = (const float*)d_in[4];
    const float* g_w2   = (const float*)d_in[5];
    const float* g_b2   = (const float*)d_in[6];
    const float* f_w1   = (const float*)d_in[7];
    const float* f_b1   = (const float*)d_in[8];
    const float* f_w2   = (const float*)d_in[9];
    const float* f_b2   = (const float*)d_in[10];
    float* out = (float*)d_out;

    static bool attr_done = false;
    if (!attr_done) {
        cudaFuncSetAttribute(pair_mma,
                             cudaFuncAttributeMaxDynamicSharedMemorySize, SMEM_PAIR);
        attr_done = true;
    }

    conv_kernel<<<NB, 256>>>(image, conv_w, conv_b);
    w2_prep<<<GH, GH>>>(g_w2);
    uv_kernel<<<NB * NPOS, 256>>>(g_w1, g_b1);
    pair_mma<<<dim3(NPOS, NB), 128, SMEM_PAIR>>>(g_b2);
    pool_kernel<<<dim3(NB, 4), 256>>>();
    head_kernel<<<NB, 256>>>(f_w1, f_b1, f_w2, f_b2, out);
}